// round 6
// baseline (speedup 1.0000x reference)
#include <cuda_runtime.h>
#include <math.h>
#include <float.h>

#define XS 2048
#define NN 4096
#define ZS 64
#define DD 6208
#define NV4 1552          // DD/4
#define TK 16
#define ZTK 8
#define EPSF 1e-9f
#define RNDF 0.5f
#define NCHUNK 64         // 32 rows per chunk
#define MIXBLK 128        // NCHUNK * 2 column-halves
#define HALF4 776         // NV4/2
#define NCAND (32 * (TK + 1))   // 544

// ---------------- device scratch (no allocations allowed) ----------------
__device__ __align__(16) float g_inpt[DD];
__device__ float g_w[DD];                 // (ages-1)/ages
__device__ __align__(16) float g_resp[DD];
__device__ __align__(16) float g_mix_x[DD];
__device__ __align__(16) float g_mix_y[DD];
__device__ __align__(16) float g_mix_z[DD];
__device__ float4 g_part4[NCHUNK][NV4];   // deterministic partial sums
__device__ float g_cval[32][TK + 1];      // per-block sorted y candidates
__device__ int   g_crow[32][TK + 1];
__device__ float g_yval[TK + 1];
__device__ int   g_yrow[TK + 1];
__device__ float g_zval[ZTK + 1];
__device__ int   g_zrow[ZTK + 1];
__device__ float g_inv_dx;

// ---------------- helpers ----------------
__device__ __forceinline__ float blockReduceSumB(float v) {
    __shared__ float red[8];
    __shared__ float bcast;
    int lane = threadIdx.x & 31;
    int wid  = threadIdx.x >> 5;
#pragma unroll
    for (int o = 16; o > 0; o >>= 1) v += __shfl_down_sync(0xffffffffu, v, o);
    if (lane == 0) red[wid] = v;
    __syncthreads();
    if (wid == 0) {
        float x = (lane < 8) ? red[lane] : 0.0f;
#pragma unroll
        for (int o = 4; o > 0; o >>= 1) x += __shfl_down_sync(0xffffffffu, x, o);
        if (lane == 0) bcast = x;
    }
    __syncthreads();
    return bcast;
}

// ---------------- K1: build inpt, weights, zero final, copy ages ----------------
__global__ void k_init(const float* __restrict__ x, const float* __restrict__ z,
                       const float* __restrict__ yresp, const float* __restrict__ ages,
                       float* __restrict__ out_z, float* __restrict__ out_final,
                       float* __restrict__ out_ages) {
    int i = blockIdx.x * 256 + threadIdx.x;
    if (i < DD) {
        float v;
        if (i < XS)           v = x[i];
        else if (i < XS + NN) v = yresp[i - XS];
        else                  v = z[i - XS - NN];
        g_inpt[i] = v;
        float a = ages[i];
        g_w[i] = (a - 1.0f) / a;
        out_final[i] = 0.0f;
        out_ages[i]  = a;
    }
    if (i < ZS) out_z[i] = 0.0f;
}

// ---------------- K2: fused mixx (blocks 0..127) + matvec/copy (blocks 128..) ----------------
__global__ void k_main(const float4* __restrict__ neu4, float* __restrict__ out_neu) {
    int t = threadIdx.x;
    int b = blockIdx.x;

    if (b < MIXBLK) {
        // ---- mix_x partials: chunk of 32 rows, one column half, float4 ----
        int chunk = b >> 1;
        int half  = b & 1;
        int r0 = chunk * 32;
        int r1 = min(r0 + 32, XS - 1);
        int cbase = half * HALF4;
        float4 acc0 = {0,0,0,0}, acc1 = {0,0,0,0}, acc2 = {0,0,0,0}, acc3 = {0,0,0,0};
        int c0 = cbase + t;
        int c1 = cbase + 256 + t;
        int c2 = cbase + 512 + t;
        int c3 = cbase + 768 + t;          // valid only for t < 8
        bool v3 = (768 + t) < HALF4;
        for (int r = r0; r < r1; r++) {
            float w = g_w[r];
            const float4* rowp = neu4 + (size_t)r * NV4;
            float4 a = __ldg(rowp + c0);
            float4 bq = __ldg(rowp + c1);
            float4 cq = __ldg(rowp + c2);
            float4 dq = v3 ? __ldg(rowp + c3) : make_float4(0,0,0,0);
            acc0.x = fmaf(w, a.x, acc0.x);  acc0.y = fmaf(w, a.y, acc0.y);
            acc0.z = fmaf(w, a.z, acc0.z);  acc0.w = fmaf(w, a.w, acc0.w);
            acc1.x = fmaf(w, bq.x, acc1.x); acc1.y = fmaf(w, bq.y, acc1.y);
            acc1.z = fmaf(w, bq.z, acc1.z); acc1.w = fmaf(w, bq.w, acc1.w);
            acc2.x = fmaf(w, cq.x, acc2.x); acc2.y = fmaf(w, cq.y, acc2.y);
            acc2.z = fmaf(w, cq.z, acc2.z); acc2.w = fmaf(w, cq.w, acc2.w);
            acc3.x = fmaf(w, dq.x, acc3.x); acc3.y = fmaf(w, dq.y, acc3.y);
            acc3.z = fmaf(w, dq.z, acc3.z); acc3.w = fmaf(w, dq.w, acc3.w);
        }
        g_part4[chunk][c0] = acc0;
        g_part4[chunk][c1] = acc1;
        g_part4[chunk][c2] = acc2;
        if (v3) g_part4[chunk][c3] = acc3;
        return;
    }

    // ---- matvec row + fused copy (skip rows < XS-1, rewritten later) ----
    int row = b - MIXBLK;
    const float4* src = neu4 + (size_t)row * NV4;
    float4* dst = reinterpret_cast<float4*>(out_neu) + (size_t)row * NV4;
    const float4* ip = reinterpret_cast<const float4*>(g_inpt);
    float acc = 0.0f;
    bool docopy = (row >= XS - 1);
#pragma unroll
    for (int j = 0; j < 7; j++) {
        int c = t + j * 256;
        if (c < NV4) {
            float4 v = __ldg(src + c);
            float4 w = ip[c];
            acc = fmaf(v.x, w.x, acc);
            acc = fmaf(v.y, w.y, acc);
            acc = fmaf(v.z, w.z, acc);
            acc = fmaf(v.w, w.w, acc);
            if (docopy) __stcs(dst + c, v);
        }
    }
    float tot = blockReduceSumB(acc);
    if (t == 0) g_resp[row] = tot;
}

// ---------------- K3: per-block sorted y top-17 via parallel rank (32 x 128) ----------------
__global__ void k_ycand() {
    __shared__ float sv[128];
    int b = blockIdx.x;       // 0..31
    int t = threadIdx.x;      // 0..127
    float v = g_resp[XS + b * 128 + t];
    sv[t] = v;
    __syncthreads();
    int rank = 0;
#pragma unroll 16
    for (int j = 0; j < 128; j++) {
        float vj = sv[j];
        rank += (vj > v) || (vj == v && j < t);
    }
    if (rank < TK + 1) {
        g_cval[b][rank] = v;
        g_crow[b][rank] = XS + b * 128 + t;
    }
}

// ---------------- K4: parallel-rank final (y merge, z top-9, x max, all finals) ----------------
__global__ void k_final(const float* __restrict__ ages, float* __restrict__ out_z,
                        float* __restrict__ out_final, float* __restrict__ out_ages) {
    __shared__ float s_v[NCAND];
    __shared__ int   s_r[NCAND];
    __shared__ float s_z[ZS];
    __shared__ float s_xv[32];
    __shared__ int   s_xnz[32];
    __shared__ float s_yv[TK + 1];
    __shared__ int   s_yr[TK + 1];
    __shared__ float s_zv[ZTK + 1];
    __shared__ int   s_zr[ZTK + 1];
    __shared__ float s_invdx;

    int t    = threadIdx.x;       // 0..1023
    int lane = t & 31;
    int wid  = t >> 5;

    // loads
    if (t < NCAND) {
        s_v[t] = ((const float*)g_cval)[t];
        s_r[t] = ((const int*)g_crow)[t];
    }
    if (t < ZS) s_z[t] = g_resp[XS + NN + t];

    // x partial max/nz per warp
    float xa = g_resp[t], xb = g_resp[t + 1024];
    {
        float bv = fmaxf(xa, xb);
        int   nz = (xa != 0.0f) | (xb != 0.0f);
#pragma unroll
        for (int o = 16; o > 0; o >>= 1) {
            bv  = fmaxf(bv, __shfl_down_sync(0xffffffffu, bv, o));
            nz |= __shfl_down_sync(0xffffffffu, nz, o);
        }
        if (lane == 0) { s_xv[wid] = bv; s_xnz[wid] = nz; }
    }
    __syncthreads();

    // parallel rank phases (disjoint thread ranges, concurrent)
    if (t < NCAND) {
        float v = s_v[t]; int row = s_r[t];
        int rank = 0;
#pragma unroll 8
        for (int j = 0; j < NCAND; j++) {
            float vj = s_v[j];
            rank += (vj > v) || (vj == v && s_r[j] < row);
        }
        if (rank < TK + 1) {
            s_yv[rank] = v; s_yr[rank] = row;
            g_yval[rank] = v; g_yrow[rank] = row;
        }
    } else if (t >= NCAND && t < NCAND + ZS) {
        int i = t - NCAND;
        float v = s_z[i];
        int rank = 0;
#pragma unroll
        for (int j = 0; j < ZS; j++) {
            float vj = s_z[j];
            rank += (vj > v) || (vj == v && j < i);
        }
        if (rank < ZTK + 1) {
            s_zv[rank] = v; s_zr[rank] = XS + NN + i;
            g_zval[rank] = v; g_zrow[rank] = XS + NN + i;
        }
    } else if (wid == 20) {
        // x final reduce
        float bv = s_xv[lane]; int nz = s_xnz[lane];
#pragma unroll
        for (int o = 16; o > 0; o >>= 1) {
            bv  = fmaxf(bv, __shfl_down_sync(0xffffffffu, bv, o));
            nz |= __shfl_down_sync(0xffffffffu, nz, o);
        }
        if (lane == 0) {
            float tx = nz ? 0.0f : 1.0f;
            float inv = 1.0f / (bv + EPSF * tx * RNDF);
            s_invdx = inv;
            g_inv_dx = inv;
        }
    }
    __syncthreads();

    // scalar finals for y/z (all from smem)
    if (t == 0) {
        float yvL = s_yv[TK];
        float ty = 0.0f;
#pragma unroll
        for (int k = 0; k < TK; k++) if (s_yv[k] == yvL) ty = 1.0f;
        float dy = 1.0f / (s_yv[0] - yvL + EPSF * ty * RNDF);
#pragma unroll
        for (int k = 0; k < TK; k++) {
            int r = s_yr[k];
            out_final[r] = (s_yv[k] - yvL) * dy;
            out_ages[r]  = ages[r] + 1.0f;
        }
        float zvL = s_zv[ZTK];
        float dz = 1.0f / (s_zv[0] - zvL);
#pragma unroll
        for (int k = 0; k < ZTK; k++) {
            int r = s_zr[k];
            float f = (s_zv[k] - zvL) * dz;
            out_final[r] = f;
            out_z[r - (XS + NN)] = f;
            out_ages[r] = ages[r] + 1.0f;
        }
    }

    // x finals + ages
    float inv = s_invdx;
    out_final[t]        = xa * inv;
    out_final[t + 1024] = xb * inv;
    out_ages[t] = ages[t] + 1.0f;                      // t <= 1023 < XS-1
    if (t + 1024 < XS - 1) out_ages[t + 1024] = ages[t + 1024] + 1.0f;
}

// ---------------- K5: reduce mix_x partials; compute mix_y, mix_z (float4) ----------------
__global__ void k_mixyz(const float4* __restrict__ neu4) {
    int c4 = blockIdx.x * 256 + threadIdx.x;
    if (c4 >= NV4) return;
    float4 mx = {0,0,0,0};
#pragma unroll
    for (int ch = 0; ch < NCHUNK; ch++) {
        float4 p = g_part4[ch][c4];
        mx.x += p.x; mx.y += p.y; mx.z += p.z; mx.w += p.w;
    }
    reinterpret_cast<float4*>(g_mix_x)[c4] = mx;

    float4 my = {0,0,0,0};
#pragma unroll
    for (int k = 0; k < TK; k++) {
        int r = g_yrow[k];
        float w = g_w[r];
        float4 v = __ldg(&neu4[(size_t)r * NV4 + c4]);
        my.x = fmaf(w, v.x, my.x); my.y = fmaf(w, v.y, my.y);
        my.z = fmaf(w, v.z, my.z); my.w = fmaf(w, v.w, my.w);
    }
    reinterpret_cast<float4*>(g_mix_y)[c4] = my;

    float4 mz = {0,0,0,0};
#pragma unroll
    for (int k = 0; k < ZTK; k++) {
        int r = g_zrow[k];
        float w = g_w[r];
        float4 v = __ldg(&neu4[(size_t)r * NV4 + c4]);
        mz.x = fmaf(w, v.x, mz.x); mz.y = fmaf(w, v.y, mz.y);
        mz.z = fmaf(w, v.z, mz.z); mz.w = fmaf(w, v.w, mz.w);
    }
    reinterpret_cast<float4*>(g_mix_z)[c4] = mz;
}

// ---------------- K6: fused row updates (x blocks 0..511, yz blocks 512..535) ----------------
__global__ void k_upd(const float* __restrict__ ages, float* __restrict__ out_neu) {
    int t = threadIdx.x;
    int b = blockIdx.x;
    const float4* ip = reinterpret_cast<const float4*>(g_inpt);

    if (b < 512) {
        // ---- x rows: 4 per block ----
        int r0 = b * 4;
        float invdx = g_inv_dx;
        const float4* mxp = reinterpret_cast<const float4*>(g_mix_x);
        for (int rr = 0; rr < 4; rr++) {
            int r = r0 + rr;
            if (r >= XS - 1) break;   // uniform across block
            float s = g_resp[r] * invdx / __ldg(&ages[r]);
            float4 v[7];
            float ssq = 0.0f;
#pragma unroll
            for (int j = 0; j < 7; j++) {
                int c4 = t + j * 256;
                if (c4 < NV4) {
                    float4 iv = ip[c4], mv = mxp[c4];
                    float4 vv;
                    vv.x = fmaf(s, iv.x, mv.x);
                    vv.y = fmaf(s, iv.y, mv.y);
                    vv.z = fmaf(s, iv.z, mv.z);
                    vv.w = fmaf(s, iv.w, mv.w);
                    v[j] = vv;
                    ssq = fmaf(vv.x, vv.x, ssq);
                    ssq = fmaf(vv.y, vv.y, ssq);
                    ssq = fmaf(vv.z, vv.z, ssq);
                    ssq = fmaf(vv.w, vv.w, ssq);
                }
            }
            float tot = blockReduceSumB(ssq);
            float inv = 1.0f / (sqrtf(tot) + 1e-12f);
            float4* dst = reinterpret_cast<float4*>(out_neu) + (size_t)r * NV4;
#pragma unroll
            for (int j = 0; j < 7; j++) {
                int c4 = t + j * 256;
                if (c4 < NV4) {
                    float4 o = v[j];
                    o.x *= inv; o.y *= inv; o.z *= inv; o.w *= inv;
                    __stcs(dst + c4, o);
                }
            }
        }
        return;
    }

    // ---- y/z rows ----
    int bb = b - 512;
    int r; float val; const float4* mix;
    if (bb < TK) { r = g_yrow[bb]; val = g_yval[bb]; mix = reinterpret_cast<const float4*>(g_mix_y); }
    else         { r = g_zrow[bb - TK]; val = g_zval[bb - TK]; mix = reinterpret_cast<const float4*>(g_mix_z); }
    float s = val / __ldg(&ages[r]);
    float4 v[7];
    float ssq = 0.0f;
#pragma unroll
    for (int j = 0; j < 7; j++) {
        int c4 = t + j * 256;
        if (c4 < NV4) {
            float4 iv = ip[c4], mv = mix[c4];
            float4 vv;
            vv.x = fmaf(s, iv.x, mv.x);
            vv.y = fmaf(s, iv.y, mv.y);
            vv.z = fmaf(s, iv.z, mv.z);
            vv.w = fmaf(s, iv.w, mv.w);
            v[j] = vv;
            ssq = fmaf(vv.x, vv.x, ssq);
            ssq = fmaf(vv.y, vv.y, ssq);
            ssq = fmaf(vv.z, vv.z, ssq);
            ssq = fmaf(vv.w, vv.w, ssq);
        }
    }
    float tot = blockReduceSumB(ssq);
    float inv = 1.0f / (sqrtf(tot) + 1e-12f);
    float4* dst = reinterpret_cast<float4*>(out_neu) + (size_t)r * NV4;
#pragma unroll
    for (int j = 0; j < 7; j++) {
        int c4 = t + j * 256;
        if (c4 < NV4) {
            float4 o = v[j];
            o.x *= inv; o.y *= inv; o.z *= inv; o.w *= inv;
            __stcs(dst + c4, o);
        }
    }
}

// ---------------- launch ----------------
extern "C" void kernel_launch(void* const* d_in, const int* in_sizes, int n_in,
                              void* d_out, int out_size) {
    (void)in_sizes; (void)n_in; (void)out_size;
    const float* x       = (const float*)d_in[0];
    const float* z       = (const float*)d_in[1];
    const float* yresp   = (const float*)d_in[2];
    const float* neurons = (const float*)d_in[3];
    const float* ages    = (const float*)d_in[4];

    float* out       = (float*)d_out;
    float* out_z     = out;                                // 64
    float* out_final = out + ZS;                           // 6208
    float* out_neu   = out + ZS + DD;                      // 6208*6208
    float* out_ages  = out + ZS + DD + (size_t)DD * DD;    // 6208

    k_init<<<(DD + 255) / 256, 256>>>(x, z, yresp, ages, out_z, out_final, out_ages);
    k_main<<<MIXBLK + DD, 256>>>((const float4*)neurons, out_neu);
    k_ycand<<<32, 128>>>();
    k_final<<<1, 1024>>>(ages, out_z, out_final, out_ages);
    k_mixyz<<<(NV4 + 255) / 256, 256>>>((const float4*)neurons);
    k_upd<<<512 + TK + ZTK, 256>>>(ages, out_neu);
}

// round 7
// speedup vs baseline: 1.2617x; 1.2617x over previous
#include <cuda_runtime.h>
#include <math.h>
#include <float.h>

#define XS 2048
#define NN 4096
#define ZS 64
#define DD 6208
#define NV4 1552          // DD/4
#define TK 16
#define ZTK 8
#define EPSF 1e-9f
#define RNDF 0.5f
#define NCHUNK 64         // 32 rows per chunk
#define MIXBLK 128        // NCHUNK * 2 column-halves
#define HALF4 776         // NV4/2
#define YBLK 16           // y candidate blocks
#define NCAND (YBLK * (TK + 1))   // 272

typedef unsigned long long u64;
typedef unsigned int u32;

// ---------------- device scratch (no allocations allowed) ----------------
__device__ __align__(16) float g_inpt[DD];
__device__ float g_w[DD];                 // (ages-1)/ages
__device__ __align__(16) float g_resp[DD];
__device__ __align__(16) float g_mix_x[DD];
__device__ __align__(16) float g_mix_y[DD];
__device__ __align__(16) float g_mix_z[DD];
__device__ float4 g_part4[NCHUNK][NV4];   // deterministic partial sums
__device__ u64   g_ckey[YBLK][TK + 1];    // per-block sorted y candidate keys
__device__ float g_yval[TK + 1];
__device__ int   g_yrow[TK + 1];
__device__ float g_zval[ZTK + 1];
__device__ int   g_zrow[ZTK + 1];
__device__ float g_inv_dx;

// ---------------- helpers ----------------
__device__ __forceinline__ float blockReduceSumB(float v) {
    __shared__ float red[8];
    __shared__ float bcast;
    int lane = threadIdx.x & 31;
    int wid  = threadIdx.x >> 5;
#pragma unroll
    for (int o = 16; o > 0; o >>= 1) v += __shfl_down_sync(0xffffffffu, v, o);
    if (lane == 0) red[wid] = v;
    __syncthreads();
    if (wid == 0) {
        float x = (lane < 8) ? red[lane] : 0.0f;
#pragma unroll
        for (int o = 4; o > 0; o >>= 1) x += __shfl_down_sync(0xffffffffu, x, o);
        if (lane == 0) bcast = x;
    }
    __syncthreads();
    return bcast;
}

// monotonic key: bigger value -> bigger key; ties -> lower row gets bigger key
__device__ __forceinline__ u64 makeKey(float v, int row) {
    u32 u = __float_as_uint(v);
    u = (u & 0x80000000u) ? ~u : (u | 0x80000000u);
    return ((u64)u << 32) | (u32)(~row);
}
__device__ __forceinline__ float keyVal(u64 k) {
    u32 u = (u32)(k >> 32);
    u32 bits = (u & 0x80000000u) ? (u ^ 0x80000000u) : ~u;
    return __uint_as_float(bits);
}
__device__ __forceinline__ int keyRow(u64 k) { return (int)~((u32)k); }

// ---------------- K1: build inpt, weights, zero final, copy ages ----------------
__global__ void k_init(const float* __restrict__ x, const float* __restrict__ z,
                       const float* __restrict__ yresp, const float* __restrict__ ages,
                       float* __restrict__ out_z, float* __restrict__ out_final,
                       float* __restrict__ out_ages) {
    int i = blockIdx.x * 256 + threadIdx.x;
    if (i < DD) {
        float v;
        if (i < XS)           v = x[i];
        else if (i < XS + NN) v = yresp[i - XS];
        else                  v = z[i - XS - NN];
        g_inpt[i] = v;
        float a = ages[i];
        g_w[i] = (a - 1.0f) / a;
        out_final[i] = 0.0f;
        out_ages[i]  = a;
    }
    if (i < ZS) out_z[i] = 0.0f;
}

// ---------------- K2: fused mixx (blocks 0..127) + matvec/copy (blocks 128..) ----------------
__global__ void k_main(const float4* __restrict__ neu4, float* __restrict__ out_neu) {
    int t = threadIdx.x;
    int b = blockIdx.x;

    if (b < MIXBLK) {
        int chunk = b >> 1;
        int half  = b & 1;
        int r0 = chunk * 32;
        int r1 = min(r0 + 32, XS - 1);
        int cbase = half * HALF4;
        float4 acc0 = {0,0,0,0}, acc1 = {0,0,0,0}, acc2 = {0,0,0,0}, acc3 = {0,0,0,0};
        int c0 = cbase + t;
        int c1 = cbase + 256 + t;
        int c2 = cbase + 512 + t;
        int c3 = cbase + 768 + t;
        bool v3 = (768 + t) < HALF4;
        for (int r = r0; r < r1; r++) {
            float w = g_w[r];
            const float4* rowp = neu4 + (size_t)r * NV4;
            float4 a = __ldg(rowp + c0);
            float4 bq = __ldg(rowp + c1);
            float4 cq = __ldg(rowp + c2);
            float4 dq = v3 ? __ldg(rowp + c3) : make_float4(0,0,0,0);
            acc0.x = fmaf(w, a.x, acc0.x);  acc0.y = fmaf(w, a.y, acc0.y);
            acc0.z = fmaf(w, a.z, acc0.z);  acc0.w = fmaf(w, a.w, acc0.w);
            acc1.x = fmaf(w, bq.x, acc1.x); acc1.y = fmaf(w, bq.y, acc1.y);
            acc1.z = fmaf(w, bq.z, acc1.z); acc1.w = fmaf(w, bq.w, acc1.w);
            acc2.x = fmaf(w, cq.x, acc2.x); acc2.y = fmaf(w, cq.y, acc2.y);
            acc2.z = fmaf(w, cq.z, acc2.z); acc2.w = fmaf(w, cq.w, acc2.w);
            acc3.x = fmaf(w, dq.x, acc3.x); acc3.y = fmaf(w, dq.y, acc3.y);
            acc3.z = fmaf(w, dq.z, acc3.z); acc3.w = fmaf(w, dq.w, acc3.w);
        }
        g_part4[chunk][c0] = acc0;
        g_part4[chunk][c1] = acc1;
        g_part4[chunk][c2] = acc2;
        if (v3) g_part4[chunk][c3] = acc3;
        return;
    }

    int row = b - MIXBLK;
    const float4* src = neu4 + (size_t)row * NV4;
    float4* dst = reinterpret_cast<float4*>(out_neu) + (size_t)row * NV4;
    const float4* ip = reinterpret_cast<const float4*>(g_inpt);
    float acc = 0.0f;
    bool docopy = (row >= XS - 1);
#pragma unroll
    for (int j = 0; j < 7; j++) {
        int c = t + j * 256;
        if (c < NV4) {
            float4 v = __ldg(src + c);
            float4 w = ip[c];
            acc = fmaf(v.x, w.x, acc);
            acc = fmaf(v.y, w.y, acc);
            acc = fmaf(v.z, w.z, acc);
            acc = fmaf(v.w, w.w, acc);
            if (docopy) __stcs(dst + c, v);
        }
    }
    float tot = blockReduceSumB(acc);
    if (t == 0) g_resp[row] = tot;
}

// ---------------- K3: per-block sorted y top-17 via key-rank (16 x 256) ----------------
__global__ void k_ycand() {
    __shared__ u64 sk[256];
    int b = blockIdx.x;       // 0..15
    int t = threadIdx.x;      // 0..255
    int row = XS + b * 256 + t;
    u64 key = makeKey(g_resp[row], row);
    sk[t] = key;
    __syncthreads();
    int rank = 0;
#pragma unroll 8
    for (int j = 0; j < 256; j++) rank += (sk[j] > key);
    if (rank < TK + 1) g_ckey[b][rank] = key;
}

// ---------------- K4: key-rank final (272 y cands, 64 z, x max, all finals) ----------------
__global__ void k_final(const float* __restrict__ ages, float* __restrict__ out_z,
                        float* __restrict__ out_final, float* __restrict__ out_ages) {
    __shared__ u64   s_k[NCAND];
    __shared__ u64   s_zk[ZS];
    __shared__ float s_xv[32];
    __shared__ int   s_xnz[32];
    __shared__ float s_yv[TK + 1];
    __shared__ int   s_yr[TK + 1];
    __shared__ float s_zv[ZTK + 1];
    __shared__ int   s_zr[ZTK + 1];
    __shared__ float s_invdx;

    int t    = threadIdx.x;       // 0..1023
    int lane = t & 31;
    int wid  = t >> 5;

    // loads
    if (t < NCAND) s_k[t] = ((const u64*)g_ckey)[t];
    if (t >= 512 && t < 512 + ZS) {
        int i = t - 512;
        int row = XS + NN + i;
        s_zk[i] = makeKey(g_resp[row], row);
    }

    // x partial max/nz per warp
    float xa = g_resp[t], xb = g_resp[t + 1024];
    {
        float bv = fmaxf(xa, xb);
        int   nz = (xa != 0.0f) | (xb != 0.0f);
#pragma unroll
        for (int o = 16; o > 0; o >>= 1) {
            bv  = fmaxf(bv, __shfl_down_sync(0xffffffffu, bv, o));
            nz |= __shfl_down_sync(0xffffffffu, nz, o);
        }
        if (lane == 0) { s_xv[wid] = bv; s_xnz[wid] = nz; }
    }
    __syncthreads();

    // concurrent disjoint phases
    if (t < NCAND) {
        u64 key = s_k[t];
        int rank = 0;
#pragma unroll 8
        for (int j = 0; j < NCAND; j++) rank += (s_k[j] > key);
        if (rank < TK + 1) {
            float v = keyVal(key); int row = keyRow(key);
            s_yv[rank] = v; s_yr[rank] = row;
            g_yval[rank] = v; g_yrow[rank] = row;
        }
    }
    if (t >= 512 && t < 512 + ZS) {
        int i = t - 512;
        u64 key = s_zk[i];
        int rank = 0;
#pragma unroll
        for (int j = 0; j < ZS; j++) rank += (s_zk[j] > key);
        if (rank < ZTK + 1) {
            float v = keyVal(key); int row = keyRow(key);
            s_zv[rank] = v; s_zr[rank] = row;
            g_zval[rank] = v; g_zrow[rank] = row;
        }
    }
    if (wid == 20) {
        float bv = s_xv[lane]; int nz = s_xnz[lane];
#pragma unroll
        for (int o = 16; o > 0; o >>= 1) {
            bv  = fmaxf(bv, __shfl_down_sync(0xffffffffu, bv, o));
            nz |= __shfl_down_sync(0xffffffffu, nz, o);
        }
        if (lane == 0) {
            float tx = nz ? 0.0f : 1.0f;
            float inv = 1.0f / (bv + EPSF * tx * RNDF);
            s_invdx = inv;
            g_inv_dx = inv;
        }
    }
    __syncthreads();

    // scalar finals for y/z
    if (t == 0) {
        float yvL = s_yv[TK];
        float ty = 0.0f;
#pragma unroll
        for (int k = 0; k < TK; k++) if (s_yv[k] == yvL) ty = 1.0f;
        float dy = 1.0f / (s_yv[0] - yvL + EPSF * ty * RNDF);
#pragma unroll
        for (int k = 0; k < TK; k++) {
            int r = s_yr[k];
            out_final[r] = (s_yv[k] - yvL) * dy;
            out_ages[r]  = ages[r] + 1.0f;
        }
        float zvL = s_zv[ZTK];
        float dz = 1.0f / (s_zv[0] - zvL);
#pragma unroll
        for (int k = 0; k < ZTK; k++) {
            int r = s_zr[k];
            float f = (s_zv[k] - zvL) * dz;
            out_final[r] = f;
            out_z[r - (XS + NN)] = f;
            out_ages[r] = ages[r] + 1.0f;
        }
    }

    // x finals + ages
    float inv = s_invdx;
    out_final[t]        = xa * inv;
    out_final[t + 1024] = xb * inv;
    out_ages[t] = ages[t] + 1.0f;                      // t <= 1023 < XS-1
    if (t + 1024 < XS - 1) out_ages[t + 1024] = ages[t + 1024] + 1.0f;
}

// ---------------- K5: reduce mix_x partials; compute mix_y, mix_z (float4) ----------------
__global__ void k_mixyz(const float4* __restrict__ neu4) {
    int c4 = blockIdx.x * 256 + threadIdx.x;
    if (c4 >= NV4) return;
    float4 mx = {0,0,0,0};
#pragma unroll
    for (int ch = 0; ch < NCHUNK; ch++) {
        float4 p = g_part4[ch][c4];
        mx.x += p.x; mx.y += p.y; mx.z += p.z; mx.w += p.w;
    }
    reinterpret_cast<float4*>(g_mix_x)[c4] = mx;

    float4 my = {0,0,0,0};
#pragma unroll
    for (int k = 0; k < TK; k++) {
        int r = g_yrow[k];
        float w = g_w[r];
        float4 v = __ldg(&neu4[(size_t)r * NV4 + c4]);
        my.x = fmaf(w, v.x, my.x); my.y = fmaf(w, v.y, my.y);
        my.z = fmaf(w, v.z, my.z); my.w = fmaf(w, v.w, my.w);
    }
    reinterpret_cast<float4*>(g_mix_y)[c4] = my;

    float4 mz = {0,0,0,0};
#pragma unroll
    for (int k = 0; k < ZTK; k++) {
        int r = g_zrow[k];
        float w = g_w[r];
        float4 v = __ldg(&neu4[(size_t)r * NV4 + c4]);
        mz.x = fmaf(w, v.x, mz.x); mz.y = fmaf(w, v.y, mz.y);
        mz.z = fmaf(w, v.z, mz.z); mz.w = fmaf(w, v.w, mz.w);
    }
    reinterpret_cast<float4*>(g_mix_z)[c4] = mz;
}

// ---------------- K6: fused row updates (x blocks 0..511, yz blocks 512..535) ----------------
__global__ void k_upd(const float* __restrict__ ages, float* __restrict__ out_neu) {
    int t = threadIdx.x;
    int b = blockIdx.x;
    const float4* ip = reinterpret_cast<const float4*>(g_inpt);

    if (b < 512) {
        int r0 = b * 4;
        float invdx = g_inv_dx;
        const float4* mxp = reinterpret_cast<const float4*>(g_mix_x);
        for (int rr = 0; rr < 4; rr++) {
            int r = r0 + rr;
            if (r >= XS - 1) break;   // uniform across block
            float s = g_resp[r] * invdx / __ldg(&ages[r]);
            float4 v[7];
            float ssq = 0.0f;
#pragma unroll
            for (int j = 0; j < 7; j++) {
                int c4 = t + j * 256;
                if (c4 < NV4) {
                    float4 iv = ip[c4], mv = mxp[c4];
                    float4 vv;
                    vv.x = fmaf(s, iv.x, mv.x);
                    vv.y = fmaf(s, iv.y, mv.y);
                    vv.z = fmaf(s, iv.z, mv.z);
                    vv.w = fmaf(s, iv.w, mv.w);
                    v[j] = vv;
                    ssq = fmaf(vv.x, vv.x, ssq);
                    ssq = fmaf(vv.y, vv.y, ssq);
                    ssq = fmaf(vv.z, vv.z, ssq);
                    ssq = fmaf(vv.w, vv.w, ssq);
                }
            }
            float tot = blockReduceSumB(ssq);
            float inv = 1.0f / (sqrtf(tot) + 1e-12f);
            float4* dst = reinterpret_cast<float4*>(out_neu) + (size_t)r * NV4;
#pragma unroll
            for (int j = 0; j < 7; j++) {
                int c4 = t + j * 256;
                if (c4 < NV4) {
                    float4 o = v[j];
                    o.x *= inv; o.y *= inv; o.z *= inv; o.w *= inv;
                    __stcs(dst + c4, o);
                }
            }
        }
        return;
    }

    int bb = b - 512;
    int r; float val; const float4* mix;
    if (bb < TK) { r = g_yrow[bb]; val = g_yval[bb]; mix = reinterpret_cast<const float4*>(g_mix_y); }
    else         { r = g_zrow[bb - TK]; val = g_zval[bb - TK]; mix = reinterpret_cast<const float4*>(g_mix_z); }
    float s = val / __ldg(&ages[r]);
    float4 v[7];
    float ssq = 0.0f;
#pragma unroll
    for (int j = 0; j < 7; j++) {
        int c4 = t + j * 256;
        if (c4 < NV4) {
            float4 iv = ip[c4], mv = mix[c4];
            float4 vv;
            vv.x = fmaf(s, iv.x, mv.x);
            vv.y = fmaf(s, iv.y, mv.y);
            vv.z = fmaf(s, iv.z, mv.z);
            vv.w = fmaf(s, iv.w, mv.w);
            v[j] = vv;
            ssq = fmaf(vv.x, vv.x, ssq);
            ssq = fmaf(vv.y, vv.y, ssq);
            ssq = fmaf(vv.z, vv.z, ssq);
            ssq = fmaf(vv.w, vv.w, ssq);
        }
    }
    float tot = blockReduceSumB(ssq);
    float inv = 1.0f / (sqrtf(tot) + 1e-12f);
    float4* dst = reinterpret_cast<float4*>(out_neu) + (size_t)r * NV4;
#pragma unroll
    for (int j = 0; j < 7; j++) {
        int c4 = t + j * 256;
        if (c4 < NV4) {
            float4 o = v[j];
            o.x *= inv; o.y *= inv; o.z *= inv; o.w *= inv;
            __stcs(dst + c4, o);
        }
    }
}

// ---------------- launch ----------------
extern "C" void kernel_launch(void* const* d_in, const int* in_sizes, int n_in,
                              void* d_out, int out_size) {
    (void)in_sizes; (void)n_in; (void)out_size;
    const float* x       = (const float*)d_in[0];
    const float* z       = (const float*)d_in[1];
    const float* yresp   = (const float*)d_in[2];
    const float* neurons = (const float*)d_in[3];
    const float* ages    = (const float*)d_in[4];

    float* out       = (float*)d_out;
    float* out_z     = out;                                // 64
    float* out_final = out + ZS;                           // 6208
    float* out_neu   = out + ZS + DD;                      // 6208*6208
    float* out_ages  = out + ZS + DD + (size_t)DD * DD;    // 6208

    k_init<<<(DD + 255) / 256, 256>>>(x, z, yresp, ages, out_z, out_final, out_ages);
    k_main<<<MIXBLK + DD, 256>>>((const float4*)neurons, out_neu);
    k_ycand<<<YBLK, 256>>>();
    k_final<<<1, 1024>>>(ages, out_z, out_final, out_ages);
    k_mixyz<<<(NV4 + 255) / 256, 256>>>((const float4*)neurons);
    k_upd<<<512 + TK + ZTK, 256>>>(ages, out_neu);
}

// round 8
// speedup vs baseline: 1.3199x; 1.0461x over previous
#include <cuda_runtime.h>
#include <math.h>
#include <float.h>

#define XS 2048
#define NN 4096
#define ZS 64
#define DD 6208
#define NV4 1552          // DD/4
#define TK 16
#define ZTK 8
#define EPSF 1e-9f
#define RNDF 0.5f
#define NCHUNK 64         // 32 rows per chunk
#define MIXBLK 128        // NCHUNK * 2 column-halves
#define HALF4 776         // NV4/2
#define YBLK 16           // y candidate blocks
#define NCAND (YBLK * (TK + 1))   // 272

typedef unsigned long long u64;
typedef unsigned int u32;

// ---------------- device scratch (no allocations allowed) ----------------
__device__ __align__(16) float g_inpt[DD];
__device__ float g_w[DD];                 // (ages-1)/ages
__device__ __align__(16) float g_resp[DD];
__device__ __align__(16) float g_mix_x[DD];
__device__ __align__(16) float g_mix_y[DD];
__device__ __align__(16) float g_mix_z[DD];
__device__ float4 g_part4[NCHUNK][NV4];   // deterministic partial sums
__device__ u64   g_ckey[YBLK][TK + 1];    // per-block sorted y candidate keys
__device__ float g_yval[TK + 1];
__device__ int   g_yrow[TK + 1];
__device__ float g_zval[ZTK + 1];
__device__ int   g_zrow[ZTK + 1];
__device__ float g_inv_dx;

// ---------------- helpers ----------------
__device__ __forceinline__ float blockReduceSumB(float v) {
    __shared__ float red[8];
    __shared__ float bcast;
    int lane = threadIdx.x & 31;
    int wid  = threadIdx.x >> 5;
#pragma unroll
    for (int o = 16; o > 0; o >>= 1) v += __shfl_down_sync(0xffffffffu, v, o);
    if (lane == 0) red[wid] = v;
    __syncthreads();
    if (wid == 0) {
        float x = (lane < 8) ? red[lane] : 0.0f;
#pragma unroll
        for (int o = 4; o > 0; o >>= 1) x += __shfl_down_sync(0xffffffffu, x, o);
        if (lane == 0) bcast = x;
    }
    __syncthreads();
    return bcast;
}

// monotonic key: bigger value -> bigger key; ties -> lower row gets bigger key
__device__ __forceinline__ u64 makeKey(float v, int row) {
    u32 u = __float_as_uint(v);
    u = (u & 0x80000000u) ? ~u : (u | 0x80000000u);
    return ((u64)u << 32) | (u32)(~row);
}
__device__ __forceinline__ float keyVal(u64 k) {
    u32 u = (u32)(k >> 32);
    u32 bits = (u & 0x80000000u) ? (u ^ 0x80000000u) : ~u;
    return __uint_as_float(bits);
}
__device__ __forceinline__ int keyRow(u64 k) { return (int)~((u32)k); }

// ---------------- K1: build inpt, weights, zero final, copy ages ----------------
__global__ void k_init(const float* __restrict__ x, const float* __restrict__ z,
                       const float* __restrict__ yresp, const float* __restrict__ ages,
                       float* __restrict__ out_z, float* __restrict__ out_final,
                       float* __restrict__ out_ages) {
    int i = blockIdx.x * 256 + threadIdx.x;
    if (i < DD) {
        float v;
        if (i < XS)           v = x[i];
        else if (i < XS + NN) v = yresp[i - XS];
        else                  v = z[i - XS - NN];
        g_inpt[i] = v;
        float a = ages[i];
        g_w[i] = (a - 1.0f) / a;
        out_final[i] = 0.0f;
        out_ages[i]  = a;
    }
    if (i < ZS) out_z[i] = 0.0f;
}

// ---------------- K2: fused mixx (blocks 0..127) + matvec/copy (blocks 128..) ----------------
__global__ void k_main(const float4* __restrict__ neu4, float* __restrict__ out_neu) {
    int t = threadIdx.x;
    int b = blockIdx.x;

    if (b < MIXBLK) {
        int chunk = b >> 1;
        int half  = b & 1;
        int r0 = chunk * 32;
        int r1 = min(r0 + 32, XS - 1);
        int cbase = half * HALF4;
        float4 acc0 = {0,0,0,0}, acc1 = {0,0,0,0}, acc2 = {0,0,0,0}, acc3 = {0,0,0,0};
        int c0 = cbase + t;
        int c1 = cbase + 256 + t;
        int c2 = cbase + 512 + t;
        int c3 = cbase + 768 + t;
        bool v3 = (768 + t) < HALF4;
        for (int r = r0; r < r1; r++) {
            float w = g_w[r];
            const float4* rowp = neu4 + (size_t)r * NV4;
            float4 a = __ldg(rowp + c0);
            float4 bq = __ldg(rowp + c1);
            float4 cq = __ldg(rowp + c2);
            float4 dq = v3 ? __ldg(rowp + c3) : make_float4(0,0,0,0);
            acc0.x = fmaf(w, a.x, acc0.x);  acc0.y = fmaf(w, a.y, acc0.y);
            acc0.z = fmaf(w, a.z, acc0.z);  acc0.w = fmaf(w, a.w, acc0.w);
            acc1.x = fmaf(w, bq.x, acc1.x); acc1.y = fmaf(w, bq.y, acc1.y);
            acc1.z = fmaf(w, bq.z, acc1.z); acc1.w = fmaf(w, bq.w, acc1.w);
            acc2.x = fmaf(w, cq.x, acc2.x); acc2.y = fmaf(w, cq.y, acc2.y);
            acc2.z = fmaf(w, cq.z, acc2.z); acc2.w = fmaf(w, cq.w, acc2.w);
            acc3.x = fmaf(w, dq.x, acc3.x); acc3.y = fmaf(w, dq.y, acc3.y);
            acc3.z = fmaf(w, dq.z, acc3.z); acc3.w = fmaf(w, dq.w, acc3.w);
        }
        g_part4[chunk][c0] = acc0;
        g_part4[chunk][c1] = acc1;
        g_part4[chunk][c2] = acc2;
        if (v3) g_part4[chunk][c3] = acc3;
        return;
    }

    int row = b - MIXBLK;
    const float4* src = neu4 + (size_t)row * NV4;
    float4* dst = reinterpret_cast<float4*>(out_neu) + (size_t)row * NV4;
    const float4* ip = reinterpret_cast<const float4*>(g_inpt);
    float acc = 0.0f;
    bool docopy = (row >= XS - 1);
#pragma unroll
    for (int j = 0; j < 7; j++) {
        int c = t + j * 256;
        if (c < NV4) {
            float4 v = __ldg(src + c);
            float4 w = ip[c];
            acc = fmaf(v.x, w.x, acc);
            acc = fmaf(v.y, w.y, acc);
            acc = fmaf(v.z, w.z, acc);
            acc = fmaf(v.w, w.w, acc);
            if (docopy) __stcs(dst + c, v);
        }
    }
    float tot = blockReduceSumB(acc);
    if (t == 0) g_resp[row] = tot;
}

// ---------------- K3: y candidates (b<16), z top-9 + finals (b=16), x max (b=17) ----------------
__global__ void k_ycand(const float* __restrict__ ages, float* __restrict__ out_z,
                        float* __restrict__ out_final, float* __restrict__ out_ages) {
    int b = blockIdx.x;
    int t = threadIdx.x;      // 0..255

    if (b < YBLK) {
        // ---- per-block sorted y top-17 via key-rank ----
        __shared__ u64 sk[256];
        int row = XS + b * 256 + t;
        u64 key = makeKey(g_resp[row], row);
        sk[t] = key;
        __syncthreads();
        int rank = 0;
#pragma unroll 8
        for (int j = 0; j < 256; j++) rank += (sk[j] > key);
        if (rank < TK + 1) g_ckey[b][rank] = key;
        return;
    }

    if (b == YBLK) {
        // ---- z top-9 + z finals ----
        __shared__ u64   zk[ZS];
        __shared__ float s_zv[ZTK + 1];
        __shared__ int   s_zr[ZTK + 1];
        if (t < ZS) {
            int row = XS + NN + t;
            u64 key = makeKey(g_resp[row], row);
            zk[t] = key;
        }
        __syncthreads();
        if (t < ZS) {
            u64 key = zk[t];
            int rank = 0;
#pragma unroll
            for (int j = 0; j < ZS; j++) rank += (zk[j] > key);
            if (rank < ZTK + 1) {
                float v = keyVal(key); int row = keyRow(key);
                s_zv[rank] = v; s_zr[rank] = row;
                g_zval[rank] = v; g_zrow[rank] = row;
            }
        }
        __syncthreads();
        if (t < ZTK) {
            float zvL = s_zv[ZTK];
            float dz = 1.0f / (s_zv[0] - zvL);
            int r = s_zr[t];
            float f = (s_zv[t] - zvL) * dz;
            out_final[r] = f;
            out_z[r - (XS + NN)] = f;
            out_ages[r] = ages[r] + 1.0f;
        }
        return;
    }

    // ---- b == YBLK+1: x max + nonzero -> g_inv_dx ----
    {
        __shared__ float s_xv[8];
        __shared__ int   s_xnz[8];
        int lane = t & 31;
        int wid  = t >> 5;
        float bv = -FLT_MAX; int nz = 0;
#pragma unroll
        for (int j = 0; j < 8; j++) {
            float v = g_resp[t + j * 256];
            bv = fmaxf(bv, v);
            nz |= (v != 0.0f);
        }
#pragma unroll
        for (int o = 16; o > 0; o >>= 1) {
            bv  = fmaxf(bv, __shfl_down_sync(0xffffffffu, bv, o));
            nz |= __shfl_down_sync(0xffffffffu, nz, o);
        }
        if (lane == 0) { s_xv[wid] = bv; s_xnz[wid] = nz; }
        __syncthreads();
        if (t == 0) {
            float m = s_xv[0]; int z = s_xnz[0];
#pragma unroll
            for (int w2 = 1; w2 < 8; w2++) { m = fmaxf(m, s_xv[w2]); z |= s_xnz[w2]; }
            float tx = z ? 0.0f : 1.0f;
            g_inv_dx = 1.0f / (m + EPSF * tx * RNDF);
        }
    }
}

// ---------------- K4: y-only final (272 candidates, 288 threads) ----------------
__global__ void k_final(const float* __restrict__ ages,
                        float* __restrict__ out_final, float* __restrict__ out_ages) {
    __shared__ u64   s_k[NCAND];
    __shared__ float s_yv[TK + 1];
    __shared__ int   s_yr[TK + 1];

    int t = threadIdx.x;      // 0..287

    if (t < NCAND) s_k[t] = ((const u64*)g_ckey)[t];
    __syncthreads();

    if (t < NCAND) {
        u64 key = s_k[t];
        int rank = 0;
#pragma unroll 8
        for (int j = 0; j < NCAND; j++) rank += (s_k[j] > key);
        if (rank < TK + 1) {
            float v = keyVal(key); int row = keyRow(key);
            s_yv[rank] = v; s_yr[rank] = row;
            g_yval[rank] = v; g_yrow[rank] = row;
        }
    }
    __syncthreads();

    // parallel y finals on warp 0
    if (t < 32) {
        float yvL = s_yv[TK];
        bool tie = (t < TK) && (s_yv[t] == yvL);
        u32 bal = __ballot_sync(0xffffffffu, tie);
        float ty = bal ? 1.0f : 0.0f;
        if (t < TK) {
            float dy = 1.0f / (s_yv[0] - yvL + EPSF * ty * RNDF);
            int r = s_yr[t];
            out_final[r] = (s_yv[t] - yvL) * dy;
            out_ages[r]  = ages[r] + 1.0f;
        }
    }
}

// ---------------- K5: reduce mix_x partials; compute mix_y, mix_z (float4) ----------------
__global__ void k_mixyz(const float4* __restrict__ neu4) {
    int c4 = blockIdx.x * 256 + threadIdx.x;
    if (c4 >= NV4) return;
    float4 mx = {0,0,0,0};
#pragma unroll
    for (int ch = 0; ch < NCHUNK; ch++) {
        float4 p = g_part4[ch][c4];
        mx.x += p.x; mx.y += p.y; mx.z += p.z; mx.w += p.w;
    }
    reinterpret_cast<float4*>(g_mix_x)[c4] = mx;

    float4 my = {0,0,0,0};
#pragma unroll
    for (int k = 0; k < TK; k++) {
        int r = g_yrow[k];
        float w = g_w[r];
        float4 v = __ldg(&neu4[(size_t)r * NV4 + c4]);
        my.x = fmaf(w, v.x, my.x); my.y = fmaf(w, v.y, my.y);
        my.z = fmaf(w, v.z, my.z); my.w = fmaf(w, v.w, my.w);
    }
    reinterpret_cast<float4*>(g_mix_y)[c4] = my;

    float4 mz = {0,0,0,0};
#pragma unroll
    for (int k = 0; k < ZTK; k++) {
        int r = g_zrow[k];
        float w = g_w[r];
        float4 v = __ldg(&neu4[(size_t)r * NV4 + c4]);
        mz.x = fmaf(w, v.x, mz.x); mz.y = fmaf(w, v.y, mz.y);
        mz.z = fmaf(w, v.z, mz.z); mz.w = fmaf(w, v.w, mz.w);
    }
    reinterpret_cast<float4*>(g_mix_z)[c4] = mz;
}

// ---------------- K6: fused row updates (x blocks 0..511, yz blocks 512..535) ----------------
__global__ void k_upd(const float* __restrict__ ages, float* __restrict__ out_neu,
                      float* __restrict__ out_final, float* __restrict__ out_ages) {
    int t = threadIdx.x;
    int b = blockIdx.x;
    const float4* ip = reinterpret_cast<const float4*>(g_inpt);

    if (b < 512) {
        int r0 = b * 4;
        float invdx = g_inv_dx;
        // last x row (2047): scaled final, no age bump, no row rewrite
        if (b == 511 && t == 0)
            out_final[XS - 1] = g_resp[XS - 1] * invdx;
        const float4* mxp = reinterpret_cast<const float4*>(g_mix_x);
        for (int rr = 0; rr < 4; rr++) {
            int r = r0 + rr;
            if (r >= XS - 1) break;   // uniform across block
            float a = __ldg(&ages[r]);
            float rsp = g_resp[r];
            if (t == 0) {
                out_final[r] = rsp * invdx;
                out_ages[r]  = a + 1.0f;
            }
            float s = rsp * invdx / a;
            float4 v[7];
            float ssq = 0.0f;
#pragma unroll
            for (int j = 0; j < 7; j++) {
                int c4 = t + j * 256;
                if (c4 < NV4) {
                    float4 iv = ip[c4], mv = mxp[c4];
                    float4 vv;
                    vv.x = fmaf(s, iv.x, mv.x);
                    vv.y = fmaf(s, iv.y, mv.y);
                    vv.z = fmaf(s, iv.z, mv.z);
                    vv.w = fmaf(s, iv.w, mv.w);
                    v[j] = vv;
                    ssq = fmaf(vv.x, vv.x, ssq);
                    ssq = fmaf(vv.y, vv.y, ssq);
                    ssq = fmaf(vv.z, vv.z, ssq);
                    ssq = fmaf(vv.w, vv.w, ssq);
                }
            }
            float tot = blockReduceSumB(ssq);
            float inv = 1.0f / (sqrtf(tot) + 1e-12f);
            float4* dst = reinterpret_cast<float4*>(out_neu) + (size_t)r * NV4;
#pragma unroll
            for (int j = 0; j < 7; j++) {
                int c4 = t + j * 256;
                if (c4 < NV4) {
                    float4 o = v[j];
                    o.x *= inv; o.y *= inv; o.z *= inv; o.w *= inv;
                    __stcs(dst + c4, o);
                }
            }
        }
        return;
    }

    int bb = b - 512;
    int r; float val; const float4* mix;
    if (bb < TK) { r = g_yrow[bb]; val = g_yval[bb]; mix = reinterpret_cast<const float4*>(g_mix_y); }
    else         { r = g_zrow[bb - TK]; val = g_zval[bb - TK]; mix = reinterpret_cast<const float4*>(g_mix_z); }
    float s = val / __ldg(&ages[r]);
    float4 v[7];
    float ssq = 0.0f;
#pragma unroll
    for (int j = 0; j < 7; j++) {
        int c4 = t + j * 256;
        if (c4 < NV4) {
            float4 iv = ip[c4], mv = mix[c4];
            float4 vv;
            vv.x = fmaf(s, iv.x, mv.x);
            vv.y = fmaf(s, iv.y, mv.y);
            vv.z = fmaf(s, iv.z, mv.z);
            vv.w = fmaf(s, iv.w, mv.w);
            v[j] = vv;
            ssq = fmaf(vv.x, vv.x, ssq);
            ssq = fmaf(vv.y, vv.y, ssq);
            ssq = fmaf(vv.z, vv.z, ssq);
            ssq = fmaf(vv.w, vv.w, ssq);
        }
    }
    float tot = blockReduceSumB(ssq);
    float inv = 1.0f / (sqrtf(tot) + 1e-12f);
    float4* dst = reinterpret_cast<float4*>(out_neu) + (size_t)r * NV4;
#pragma unroll
    for (int j = 0; j < 7; j++) {
        int c4 = t + j * 256;
        if (c4 < NV4) {
            float4 o = v[j];
            o.x *= inv; o.y *= inv; o.z *= inv; o.w *= inv;
            __stcs(dst + c4, o);
        }
    }
}

// ---------------- launch ----------------
extern "C" void kernel_launch(void* const* d_in, const int* in_sizes, int n_in,
                              void* d_out, int out_size) {
    (void)in_sizes; (void)n_in; (void)out_size;
    const float* x       = (const float*)d_in[0];
    const float* z       = (const float*)d_in[1];
    const float* yresp   = (const float*)d_in[2];
    const float* neurons = (const float*)d_in[3];
    const float* ages    = (const float*)d_in[4];

    float* out       = (float*)d_out;
    float* out_z     = out;                                // 64
    float* out_final = out + ZS;                           // 6208
    float* out_neu   = out + ZS + DD;                      // 6208*6208
    float* out_ages  = out + ZS + DD + (size_t)DD * DD;    // 6208

    k_init<<<(DD + 255) / 256, 256>>>(x, z, yresp, ages, out_z, out_final, out_ages);
    k_main<<<MIXBLK + DD, 256>>>((const float4*)neurons, out_neu);
    k_ycand<<<YBLK + 2, 256>>>(ages, out_z, out_final, out_ages);
    k_final<<<1, 288>>>(ages, out_final, out_ages);
    k_mixyz<<<(NV4 + 255) / 256, 256>>>((const float4*)neurons);
    k_upd<<<512 + TK + ZTK, 256>>>(ages, out_neu, out_final, out_ages);
}

// round 9
// speedup vs baseline: 1.3626x; 1.0324x over previous
#include <cuda_runtime.h>
#include <math.h>
#include <float.h>

#define XS 2048
#define NN 4096
#define ZS 64
#define DD 6208
#define NV4 1552          // DD/4
#define TK 16
#define ZTK 8
#define EPSF 1e-9f
#define RNDF 0.5f
#define NCHUNK 64         // 32 rows per chunk
#define MIXBLK 128        // NCHUNK * 2 column-halves
#define HALF4 776         // NV4/2
#define YBLK 16           // y candidate blocks
#define NCAND (YBLK * (TK + 1))   // 272
#define RSPAN 91          // ceil(272/3)

typedef unsigned long long u64;
typedef unsigned int u32;

// ---------------- device scratch (no allocations allowed) ----------------
__device__ __align__(16) float g_inpt[DD];
__device__ float g_w[DD];                 // (ages-1)/ages
__device__ __align__(16) float g_resp[DD];
__device__ __align__(16) float g_mix_x[DD];
__device__ __align__(16) float g_mix_y[DD];
__device__ __align__(16) float g_mix_z[DD];
__device__ float4 g_part4[NCHUNK][NV4];   // deterministic partial sums
__device__ u64   g_ckey[YBLK][TK + 1];    // per-block sorted y candidate keys
__device__ float g_yval[TK + 1];
__device__ int   g_yrow[TK + 1];
__device__ float g_zval[ZTK + 1];
__device__ int   g_zrow[ZTK + 1];
__device__ float g_inv_dx;
__device__ float g_dots[3];               // |mix_x|^2, mix_x.inpt, |inpt|^2

// ---------------- helpers ----------------
__device__ __forceinline__ float blockReduceSumB(float v) {
    __shared__ float red[32];
    __shared__ float bcast;
    int lane = threadIdx.x & 31;
    int wid  = threadIdx.x >> 5;
    int nw   = blockDim.x >> 5;
#pragma unroll
    for (int o = 16; o > 0; o >>= 1) v += __shfl_down_sync(0xffffffffu, v, o);
    if (lane == 0) red[wid] = v;
    __syncthreads();
    if (wid == 0) {
        float x = (lane < nw) ? red[lane] : 0.0f;
#pragma unroll
        for (int o = 16; o > 0; o >>= 1) x += __shfl_down_sync(0xffffffffu, x, o);
        if (lane == 0) bcast = x;
    }
    __syncthreads();
    return bcast;
}

// monotonic key: bigger value -> bigger key; ties -> lower row gets bigger key
__device__ __forceinline__ u64 makeKey(float v, int row) {
    u32 u = __float_as_uint(v);
    u = (u & 0x80000000u) ? ~u : (u | 0x80000000u);
    return ((u64)u << 32) | (u32)(~row);
}
__device__ __forceinline__ float keyVal(u64 k) {
    u32 u = (u32)(k >> 32);
    u32 bits = (u & 0x80000000u) ? (u ^ 0x80000000u) : ~u;
    return __uint_as_float(bits);
}
__device__ __forceinline__ int keyRow(u64 k) { return (int)~((u32)k); }

// ---------------- K1: build inpt, weights, zero final, copy ages ----------------
__global__ void k_init(const float* __restrict__ x, const float* __restrict__ z,
                       const float* __restrict__ yresp, const float* __restrict__ ages,
                       float* __restrict__ out_z, float* __restrict__ out_final,
                       float* __restrict__ out_ages) {
    int i = blockIdx.x * 256 + threadIdx.x;
    if (i < DD) {
        float v;
        if (i < XS)           v = x[i];
        else if (i < XS + NN) v = yresp[i - XS];
        else                  v = z[i - XS - NN];
        g_inpt[i] = v;
        float a = ages[i];
        g_w[i] = (a - 1.0f) / a;
        out_final[i] = 0.0f;
        out_ages[i]  = a;
    }
    if (i < ZS) out_z[i] = 0.0f;
}

// ---------------- K2: fused mixx partials (blocks 0..127) + matvec/copy ----------------
__global__ void k_main(const float4* __restrict__ neu4, float* __restrict__ out_neu) {
    int t = threadIdx.x;
    int b = blockIdx.x;

    if (b < MIXBLK) {
        int chunk = b >> 1;
        int half  = b & 1;
        int r0 = chunk * 32;
        int r1 = min(r0 + 32, XS - 1);
        int cbase = half * HALF4;
        float4 acc0 = {0,0,0,0}, acc1 = {0,0,0,0}, acc2 = {0,0,0,0}, acc3 = {0,0,0,0};
        int c0 = cbase + t;
        int c1 = cbase + 256 + t;
        int c2 = cbase + 512 + t;
        int c3 = cbase + 768 + t;
        bool v3 = (768 + t) < HALF4;
        for (int r = r0; r < r1; r++) {
            float w = g_w[r];
            const float4* rowp = neu4 + (size_t)r * NV4;
            float4 a = __ldg(rowp + c0);
            float4 bq = __ldg(rowp + c1);
            float4 cq = __ldg(rowp + c2);
            float4 dq = v3 ? __ldg(rowp + c3) : make_float4(0,0,0,0);
            acc0.x = fmaf(w, a.x, acc0.x);  acc0.y = fmaf(w, a.y, acc0.y);
            acc0.z = fmaf(w, a.z, acc0.z);  acc0.w = fmaf(w, a.w, acc0.w);
            acc1.x = fmaf(w, bq.x, acc1.x); acc1.y = fmaf(w, bq.y, acc1.y);
            acc1.z = fmaf(w, bq.z, acc1.z); acc1.w = fmaf(w, bq.w, acc1.w);
            acc2.x = fmaf(w, cq.x, acc2.x); acc2.y = fmaf(w, cq.y, acc2.y);
            acc2.z = fmaf(w, cq.z, acc2.z); acc2.w = fmaf(w, cq.w, acc2.w);
            acc3.x = fmaf(w, dq.x, acc3.x); acc3.y = fmaf(w, dq.y, acc3.y);
            acc3.z = fmaf(w, dq.z, acc3.z); acc3.w = fmaf(w, dq.w, acc3.w);
        }
        g_part4[chunk][c0] = acc0;
        g_part4[chunk][c1] = acc1;
        g_part4[chunk][c2] = acc2;
        if (v3) g_part4[chunk][c3] = acc3;
        return;
    }

    int row = b - MIXBLK;
    const float4* src = neu4 + (size_t)row * NV4;
    float4* dst = reinterpret_cast<float4*>(out_neu) + (size_t)row * NV4;
    const float4* ip = reinterpret_cast<const float4*>(g_inpt);
    float acc = 0.0f;
    bool docopy = (row >= XS - 1);
#pragma unroll
    for (int j = 0; j < 7; j++) {
        int c = t + j * 256;
        if (c < NV4) {
            float4 v = __ldg(src + c);
            float4 w = ip[c];
            acc = fmaf(v.x, w.x, acc);
            acc = fmaf(v.y, w.y, acc);
            acc = fmaf(v.z, w.z, acc);
            acc = fmaf(v.w, w.w, acc);
            if (docopy) __stcs(dst + c, v);
        }
    }
    float tot = blockReduceSumB(acc);
    if (t == 0) g_resp[row] = tot;
}

// ---------------- K3: y cands (b<16), z (b=16), x max (b=17), mix_x reduce (b=18..24) ----------------
__global__ void k_ycand(const float* __restrict__ ages, float* __restrict__ out_z,
                        float* __restrict__ out_final, float* __restrict__ out_ages) {
    int b = blockIdx.x;
    int t = threadIdx.x;      // 0..255

    if (b < YBLK) {
        __shared__ u64 sk[256];
        int row = XS + b * 256 + t;
        u64 key = makeKey(g_resp[row], row);
        sk[t] = key;
        __syncthreads();
        int rank = 0;
#pragma unroll 8
        for (int j = 0; j < 256; j++) rank += (sk[j] > key);
        if (rank < TK + 1) g_ckey[b][rank] = key;
        return;
    }

    if (b == YBLK) {
        // ---- z top-9 + z finals ----
        __shared__ u64   zk[ZS];
        __shared__ float s_zv[ZTK + 1];
        __shared__ int   s_zr[ZTK + 1];
        if (t < ZS) {
            int row = XS + NN + t;
            zk[t] = makeKey(g_resp[row], row);
        }
        __syncthreads();
        if (t < ZS) {
            u64 key = zk[t];
            int rank = 0;
#pragma unroll
            for (int j = 0; j < ZS; j++) rank += (zk[j] > key);
            if (rank < ZTK + 1) {
                float v = keyVal(key); int row = keyRow(key);
                s_zv[rank] = v; s_zr[rank] = row;
                g_zval[rank] = v; g_zrow[rank] = row;
            }
        }
        __syncthreads();
        if (t < ZTK) {
            float zvL = s_zv[ZTK];
            float dz = 1.0f / (s_zv[0] - zvL);
            int r = s_zr[t];
            float f = (s_zv[t] - zvL) * dz;
            out_final[r] = f;
            out_z[r - (XS + NN)] = f;
            out_ages[r] = ages[r] + 1.0f;
        }
        return;
    }

    if (b == YBLK + 1) {
        // ---- x max + nonzero -> g_inv_dx ----
        __shared__ float s_xv[8];
        __shared__ int   s_xnz[8];
        int lane = t & 31;
        int wid  = t >> 5;
        float bv = -FLT_MAX; int nz = 0;
#pragma unroll
        for (int j = 0; j < 8; j++) {
            float v = g_resp[t + j * 256];
            bv = fmaxf(bv, v);
            nz |= (v != 0.0f);
        }
#pragma unroll
        for (int o = 16; o > 0; o >>= 1) {
            bv  = fmaxf(bv, __shfl_down_sync(0xffffffffu, bv, o));
            nz |= __shfl_down_sync(0xffffffffu, nz, o);
        }
        if (lane == 0) { s_xv[wid] = bv; s_xnz[wid] = nz; }
        __syncthreads();
        if (t == 0) {
            float m = s_xv[0]; int z = s_xnz[0];
#pragma unroll
            for (int w2 = 1; w2 < 8; w2++) { m = fmaxf(m, s_xv[w2]); z |= s_xnz[w2]; }
            float tx = z ? 0.0f : 1.0f;
            g_inv_dx = 1.0f / (m + EPSF * tx * RNDF);
        }
        return;
    }

    // ---- b in 18..24: reduce mix_x partials (float4 columns) ----
    {
        int c4 = (b - (YBLK + 2)) * 256 + t;
        if (c4 < NV4) {
            float4 mx = {0,0,0,0};
#pragma unroll
            for (int ch = 0; ch < NCHUNK; ch++) {
                float4 p = g_part4[ch][c4];
                mx.x += p.x; mx.y += p.y; mx.z += p.z; mx.w += p.w;
            }
            reinterpret_cast<float4*>(g_mix_x)[c4] = mx;
        }
    }
}

// ---------------- K4: block 0 = y merge (3-way split rank); block 1 = x dots ----------------
__global__ void k_final(const float* __restrict__ ages,
                        float* __restrict__ out_final, float* __restrict__ out_ages) {
    int t = threadIdx.x;      // 0..1023

    if (blockIdx.x == 1) {
        // ---- dots: |mix_x|^2, mix_x.inpt, |inpt|^2 (deterministic fixed-order) ----
        float dxx = 0.0f, dxi = 0.0f, dii = 0.0f;
        for (int i = t; i < DD; i += 1024) {
            float m = g_mix_x[i];
            float p = g_inpt[i];
            dxx = fmaf(m, m, dxx);
            dxi = fmaf(m, p, dxi);
            dii = fmaf(p, p, dii);
        }
        float sxx = blockReduceSumB(dxx);
        float sxi = blockReduceSumB(dxi);
        float sii = blockReduceSumB(dii);
        if (t == 0) { g_dots[0] = sxx; g_dots[1] = sxi; g_dots[2] = sii; }
        return;
    }

    // ---- block 0: y merge ----
    __shared__ u64   s_k[NCAND];
    __shared__ short s_pr[3 * NCAND];
    __shared__ float s_yv[TK + 1];
    __shared__ int   s_yr[TK + 1];

    if (t < NCAND) s_k[t] = ((const u64*)g_ckey)[t];
    __syncthreads();

    if (t < 3 * NCAND) {
        int cand = t % NCAND;
        int part = t / NCAND;
        u64 key = s_k[cand];
        int j0 = part * RSPAN;
        int j1 = min(j0 + RSPAN, NCAND);
        int rank = 0;
        for (int j = j0; j < j1; j++) rank += (s_k[j] > key);
        s_pr[t] = (short)rank;
    }
    __syncthreads();

    if (t < NCAND) {
        int rank = s_pr[t] + s_pr[t + NCAND] + s_pr[t + 2 * NCAND];
        if (rank < TK + 1) {
            u64 key = s_k[t];
            float v = keyVal(key); int row = keyRow(key);
            s_yv[rank] = v; s_yr[rank] = row;
            g_yval[rank] = v; g_yrow[rank] = row;
        }
    }
    __syncthreads();

    // parallel y finals on warp 0
    if (t < 32) {
        float yvL = s_yv[TK];
        bool tie = (t < TK) && (s_yv[t] == yvL);
        u32 bal = __ballot_sync(0xffffffffu, tie);
        float ty = bal ? 1.0f : 0.0f;
        if (t < TK) {
            float dy = 1.0f / (s_yv[0] - yvL + EPSF * ty * RNDF);
            int r = s_yr[t];
            out_final[r] = (s_yv[t] - yvL) * dy;
            out_ages[r]  = ages[r] + 1.0f;
        }
    }
}

// ---------------- K5: mix_y, mix_z (float4) ----------------
__global__ void k_mixyz(const float4* __restrict__ neu4) {
    int c4 = blockIdx.x * 256 + threadIdx.x;
    if (c4 >= NV4) return;
    float4 my = {0,0,0,0};
#pragma unroll
    for (int k = 0; k < TK; k++) {
        int r = g_yrow[k];
        float w = g_w[r];
        float4 v = __ldg(&neu4[(size_t)r * NV4 + c4]);
        my.x = fmaf(w, v.x, my.x); my.y = fmaf(w, v.y, my.y);
        my.z = fmaf(w, v.z, my.z); my.w = fmaf(w, v.w, my.w);
    }
    reinterpret_cast<float4*>(g_mix_y)[c4] = my;

    float4 mz = {0,0,0,0};
#pragma unroll
    for (int k = 0; k < ZTK; k++) {
        int r = g_zrow[k];
        float w = g_w[r];
        float4 v = __ldg(&neu4[(size_t)r * NV4 + c4]);
        mz.x = fmaf(w, v.x, mz.x); mz.y = fmaf(w, v.y, mz.y);
        mz.z = fmaf(w, v.z, mz.z); mz.w = fmaf(w, v.w, mz.w);
    }
    reinterpret_cast<float4*>(g_mix_z)[c4] = mz;
}

// ---------------- K6: fused row updates (x blocks 0..511 streaming; yz 512..535) ----------------
__global__ void k_upd(const float* __restrict__ ages, float* __restrict__ out_neu,
                      float* __restrict__ out_final, float* __restrict__ out_ages) {
    int t = threadIdx.x;
    int b = blockIdx.x;
    const float4* ip = reinterpret_cast<const float4*>(g_inpt);

    if (b < 512) {
        int r0 = b * 4;
        float invdx = g_inv_dx;
        float dxx = g_dots[0], dxi = g_dots[1], dii = g_dots[2];
        // last x row (2047): scaled final only
        if (b == 511 && t == 0)
            out_final[XS - 1] = g_resp[XS - 1] * invdx;
        const float4* mxp = reinterpret_cast<const float4*>(g_mix_x);
#pragma unroll 1
        for (int rr = 0; rr < 4; rr++) {
            int r = r0 + rr;
            if (r >= XS - 1) break;   // uniform across block
            float a = __ldg(&ages[r]);
            float rsp = g_resp[r];
            if (t == 0) {
                out_final[r] = rsp * invdx;
                out_ages[r]  = a + 1.0f;
            }
            float s = rsp * invdx / a;
            float ssq = dxx + 2.0f * s * dxi + s * s * dii;
            float inv = 1.0f / (sqrtf(ssq) + 1e-12f);
            float si = s * inv;
            float4* dst = reinterpret_cast<float4*>(out_neu) + (size_t)r * NV4;
#pragma unroll
            for (int j = 0; j < 7; j++) {
                int c4 = t + j * 256;
                if (c4 < NV4) {
                    float4 iv = ip[c4], mv = mxp[c4];
                    float4 o;
                    o.x = fmaf(si, iv.x, mv.x * inv);
                    o.y = fmaf(si, iv.y, mv.y * inv);
                    o.z = fmaf(si, iv.z, mv.z * inv);
                    o.w = fmaf(si, iv.w, mv.w * inv);
                    __stcs(dst + c4, o);
                }
            }
        }
        return;
    }

    int bb = b - 512;
    int r; float val; const float4* mix;
    if (bb < TK) { r = g_yrow[bb]; val = g_yval[bb]; mix = reinterpret_cast<const float4*>(g_mix_y); }
    else         { r = g_zrow[bb - TK]; val = g_zval[bb - TK]; mix = reinterpret_cast<const float4*>(g_mix_z); }
    float s = val / __ldg(&ages[r]);
    float4 v[7];
    float ssq = 0.0f;
#pragma unroll
    for (int j = 0; j < 7; j++) {
        int c4 = t + j * 256;
        if (c4 < NV4) {
            float4 iv = ip[c4], mv = mix[c4];
            float4 vv;
            vv.x = fmaf(s, iv.x, mv.x);
            vv.y = fmaf(s, iv.y, mv.y);
            vv.z = fmaf(s, iv.z, mv.z);
            vv.w = fmaf(s, iv.w, mv.w);
            v[j] = vv;
            ssq = fmaf(vv.x, vv.x, ssq);
            ssq = fmaf(vv.y, vv.y, ssq);
            ssq = fmaf(vv.z, vv.z, ssq);
            ssq = fmaf(vv.w, vv.w, ssq);
        }
    }
    float tot = blockReduceSumB(ssq);
    float inv = 1.0f / (sqrtf(tot) + 1e-12f);
    float4* dst = reinterpret_cast<float4*>(out_neu) + (size_t)r * NV4;
#pragma unroll
    for (int j = 0; j < 7; j++) {
        int c4 = t + j * 256;
        if (c4 < NV4) {
            float4 o = v[j];
            o.x *= inv; o.y *= inv; o.z *= inv; o.w *= inv;
            __stcs(dst + c4, o);
        }
    }
}

// ---------------- launch ----------------
extern "C" void kernel_launch(void* const* d_in, const int* in_sizes, int n_in,
                              void* d_out, int out_size) {
    (void)in_sizes; (void)n_in; (void)out_size;
    const float* x       = (const float*)d_in[0];
    const float* z       = (const float*)d_in[1];
    const float* yresp   = (const float*)d_in[2];
    const float* neurons = (const float*)d_in[3];
    const float* ages    = (const float*)d_in[4];

    float* out       = (float*)d_out;
    float* out_z     = out;                                // 64
    float* out_final = out + ZS;                           // 6208
    float* out_neu   = out + ZS + DD;                      // 6208*6208
    float* out_ages  = out + ZS + DD + (size_t)DD * DD;    // 6208

    k_init<<<(DD + 255) / 256, 256>>>(x, z, yresp, ages, out_z, out_final, out_ages);
    k_main<<<MIXBLK + DD, 256>>>((const float4*)neurons, out_neu);
    k_ycand<<<YBLK + 2 + 7, 256>>>(ages, out_z, out_final, out_ages);
    k_final<<<2, 1024>>>(ages, out_final, out_ages);
    k_mixyz<<<(NV4 + 255) / 256, 256>>>((const float4*)neurons);
    k_upd<<<512 + TK + ZTK, 256>>>(ages, out_neu, out_final, out_ages);
}

// round 10
// speedup vs baseline: 1.5800x; 1.1596x over previous
#include <cuda_runtime.h>
#include <math.h>
#include <float.h>

#define XS 2048
#define NN 4096
#define ZS 64
#define DD 6208
#define NV4 1552          // DD/4
#define TK 16
#define ZTK 8
#define EPSF 1e-9f
#define RNDF 0.5f
#define NCHUNK 64         // 32 rows per chunk
#define MIXBLK 128        // NCHUNK * 2 column-halves
#define HALF4 776         // NV4/2
#define YBLK 16           // y candidate blocks
#define NCAND (YBLK * (TK + 1))   // 272

// k_post block roles
#define B_RED0   0        // 7 blocks: mix_x reduce
#define B_DOTS   7        // 1 block: dots (waits c_red==7)
#define B_YC0    8        // 16 blocks: y candidates
#define B_Z      24       // z top-9 + finals
#define B_XM     25       // x max -> inv_dx
#define B_YM     26       // y merge (waits c_yc==16)
#define B_MYZ0   27       // 7 blocks: mix_y/mix_z (waits c_y && c_z)
#define B_XU0    34       // 512 blocks: x updates (waits c_dots && c_x)
#define B_YZ0    546      // 24 blocks: yz updates (waits c_myz==7)
#define NPOST    570

typedef unsigned long long u64;
typedef unsigned int u32;

// ---------------- device scratch (no allocations allowed) ----------------
__device__ __align__(16) float g_inpt[DD];
__device__ float g_w[DD];                 // (ages-1)/ages
__device__ __align__(16) float g_resp[DD];
__device__ __align__(16) float g_mix_x[DD];
__device__ __align__(16) float g_mix_y[DD];
__device__ __align__(16) float g_mix_z[DD];
__device__ float4 g_part4[NCHUNK][NV4];   // deterministic partial sums
__device__ u64   g_ckey[YBLK][TK + 1];    // per-block sorted y candidate keys
__device__ float g_yval[TK + 1];
__device__ int   g_yrow[TK + 1];
__device__ float g_zval[ZTK + 1];
__device__ int   g_zrow[ZTK + 1];
__device__ float g_inv_dx;
__device__ float g_dots[3];               // |mix_x|^2, mix_x.inpt, |inpt|^2
// dependency counters
__device__ int c_red, c_dots, c_yc, c_y, c_z, c_x, c_myz;

// ---------------- helpers ----------------
__device__ __forceinline__ float blockReduceSumB(float v) {
    __shared__ float red[32];
    __shared__ float bcast;
    int lane = threadIdx.x & 31;
    int wid  = threadIdx.x >> 5;
    int nw   = blockDim.x >> 5;
#pragma unroll
    for (int o = 16; o > 0; o >>= 1) v += __shfl_down_sync(0xffffffffu, v, o);
    if (lane == 0) red[wid] = v;
    __syncthreads();
    if (wid == 0) {
        float x = (lane < nw) ? red[lane] : 0.0f;
#pragma unroll
        for (int o = 16; o > 0; o >>= 1) x += __shfl_down_sync(0xffffffffu, x, o);
        if (lane == 0) bcast = x;
    }
    __syncthreads();
    return bcast;
}

// monotonic key: bigger value -> bigger key; ties -> lower row gets bigger key
__device__ __forceinline__ u64 makeKey(float v, int row) {
    u32 u = __float_as_uint(v);
    u = (u & 0x80000000u) ? ~u : (u | 0x80000000u);
    return ((u64)u << 32) | (u32)(~row);
}
__device__ __forceinline__ float keyVal(u64 k) {
    u32 u = (u32)(k >> 32);
    u32 bits = (u & 0x80000000u) ? (u ^ 0x80000000u) : ~u;
    return __uint_as_float(bits);
}
__device__ __forceinline__ int keyRow(u64 k) { return (int)~((u32)k); }

// producer: all threads wrote data -> fence each thread -> sync -> one atomic inc
__device__ __forceinline__ void signalCnt(int* c) {
    __threadfence();
    __syncthreads();
    if (threadIdx.x == 0) atomicAdd(c, 1);
}
// consumer: thread0 spins at L2 via atomic read, then block proceeds
__device__ __forceinline__ void waitCnt(int* c, int target) {
    if (threadIdx.x == 0) {
        while (atomicAdd(c, 0) < target) __nanosleep(64);
    }
    __syncthreads();
}

// ---------------- K1: build inpt, weights, zero final/counters, copy ages ----------------
__global__ void k_init(const float* __restrict__ x, const float* __restrict__ z,
                       const float* __restrict__ yresp, const float* __restrict__ ages,
                       float* __restrict__ out_z, float* __restrict__ out_final,
                       float* __restrict__ out_ages) {
    int i = blockIdx.x * 256 + threadIdx.x;
    if (i < DD) {
        float v;
        if (i < XS)           v = x[i];
        else if (i < XS + NN) v = yresp[i - XS];
        else                  v = z[i - XS - NN];
        g_inpt[i] = v;
        float a = ages[i];
        g_w[i] = (a - 1.0f) / a;
        out_final[i] = 0.0f;
        out_ages[i]  = a;
    }
    if (i < ZS) out_z[i] = 0.0f;
    if (i == 0) { c_red = 0; c_dots = 0; c_yc = 0; c_y = 0; c_z = 0; c_x = 0; c_myz = 0; }
}

// ---------------- K2: fused mixx partials (blocks 0..127) + matvec/copy ----------------
__global__ void k_main(const float4* __restrict__ neu4, float* __restrict__ out_neu) {
    int t = threadIdx.x;
    int b = blockIdx.x;

    if (b < MIXBLK) {
        int chunk = b >> 1;
        int half  = b & 1;
        int r0 = chunk * 32;
        int r1 = min(r0 + 32, XS - 1);
        int cbase = half * HALF4;
        float4 acc0 = {0,0,0,0}, acc1 = {0,0,0,0}, acc2 = {0,0,0,0}, acc3 = {0,0,0,0};
        int c0 = cbase + t;
        int c1 = cbase + 256 + t;
        int c2 = cbase + 512 + t;
        int c3 = cbase + 768 + t;
        bool v3 = (768 + t) < HALF4;
        for (int r = r0; r < r1; r++) {
            float w = g_w[r];
            const float4* rowp = neu4 + (size_t)r * NV4;
            float4 a = __ldg(rowp + c0);
            float4 bq = __ldg(rowp + c1);
            float4 cq = __ldg(rowp + c2);
            float4 dq = v3 ? __ldg(rowp + c3) : make_float4(0,0,0,0);
            acc0.x = fmaf(w, a.x, acc0.x);  acc0.y = fmaf(w, a.y, acc0.y);
            acc0.z = fmaf(w, a.z, acc0.z);  acc0.w = fmaf(w, a.w, acc0.w);
            acc1.x = fmaf(w, bq.x, acc1.x); acc1.y = fmaf(w, bq.y, acc1.y);
            acc1.z = fmaf(w, bq.z, acc1.z); acc1.w = fmaf(w, bq.w, acc1.w);
            acc2.x = fmaf(w, cq.x, acc2.x); acc2.y = fmaf(w, cq.y, acc2.y);
            acc2.z = fmaf(w, cq.z, acc2.z); acc2.w = fmaf(w, cq.w, acc2.w);
            acc3.x = fmaf(w, dq.x, acc3.x); acc3.y = fmaf(w, dq.y, acc3.y);
            acc3.z = fmaf(w, dq.z, acc3.z); acc3.w = fmaf(w, dq.w, acc3.w);
        }
        g_part4[chunk][c0] = acc0;
        g_part4[chunk][c1] = acc1;
        g_part4[chunk][c2] = acc2;
        if (v3) g_part4[chunk][c3] = acc3;
        return;
    }

    int row = b - MIXBLK;
    const float4* src = neu4 + (size_t)row * NV4;
    float4* dst = reinterpret_cast<float4*>(out_neu) + (size_t)row * NV4;
    const float4* ip = reinterpret_cast<const float4*>(g_inpt);
    float acc = 0.0f;
    bool docopy = (row >= XS - 1);
#pragma unroll
    for (int j = 0; j < 7; j++) {
        int c = t + j * 256;
        if (c < NV4) {
            float4 v = __ldg(src + c);
            float4 w = ip[c];
            acc = fmaf(v.x, w.x, acc);
            acc = fmaf(v.y, w.y, acc);
            acc = fmaf(v.z, w.z, acc);
            acc = fmaf(v.w, w.w, acc);
            if (docopy) __stcs(dst + c, v);
        }
    }
    float tot = blockReduceSumB(acc);
    if (t == 0) g_resp[row] = tot;
}

// ---------------- K3: single fused post-kernel (all selection + mixes + updates) ----------------
__global__ void k_post(const float* __restrict__ ages, const float4* __restrict__ neu4,
                       float* __restrict__ out_z, float* __restrict__ out_final,
                       float* __restrict__ out_ages, float* __restrict__ out_neu) {
    int t = threadIdx.x;      // 0..255
    int b = blockIdx.x;
    const float4* ip = reinterpret_cast<const float4*>(g_inpt);

    // ======== x update blocks (bulk of work) ========
    if (b >= B_XU0 && b < B_YZ0) {
        waitCnt(&c_dots, 1);
        waitCnt(&c_x, 1);
        int r0 = (b - B_XU0) * 4;
        float invdx = g_inv_dx;
        float dxx = g_dots[0], dxi = g_dots[1], dii = g_dots[2];
        if (b == B_YZ0 - 1 && t == 0)
            out_final[XS - 1] = g_resp[XS - 1] * invdx;   // last x row: final only
        const float4* mxp = reinterpret_cast<const float4*>(g_mix_x);
#pragma unroll 1
        for (int rr = 0; rr < 4; rr++) {
            int r = r0 + rr;
            if (r >= XS - 1) break;   // uniform across block
            float a = __ldg(&ages[r]);
            float rsp = g_resp[r];
            if (t == 0) {
                out_final[r] = rsp * invdx;
                out_ages[r]  = a + 1.0f;
            }
            float s = rsp * invdx / a;
            float ssq = dxx + 2.0f * s * dxi + s * s * dii;
            float inv = 1.0f / (sqrtf(ssq) + 1e-12f);
            float si = s * inv;
            float4* dst = reinterpret_cast<float4*>(out_neu) + (size_t)r * NV4;
#pragma unroll
            for (int j = 0; j < 7; j++) {
                int c4 = t + j * 256;
                if (c4 < NV4) {
                    float4 iv = ip[c4], mv = mxp[c4];
                    float4 o;
                    o.x = fmaf(si, iv.x, mv.x * inv);
                    o.y = fmaf(si, iv.y, mv.y * inv);
                    o.z = fmaf(si, iv.z, mv.z * inv);
                    o.w = fmaf(si, iv.w, mv.w * inv);
                    __stcs(dst + c4, o);
                }
            }
        }
        return;
    }

    // ======== yz update blocks ========
    if (b >= B_YZ0) {
        waitCnt(&c_myz, 7);
        int bb = b - B_YZ0;
        int r; float val; const float4* mix;
        if (bb < TK) { r = g_yrow[bb]; val = g_yval[bb]; mix = reinterpret_cast<const float4*>(g_mix_y); }
        else         { r = g_zrow[bb - TK]; val = g_zval[bb - TK]; mix = reinterpret_cast<const float4*>(g_mix_z); }
        float s = val / __ldg(&ages[r]);
        float4 v[7];
        float ssq = 0.0f;
#pragma unroll
        for (int j = 0; j < 7; j++) {
            int c4 = t + j * 256;
            if (c4 < NV4) {
                float4 iv = ip[c4], mv = mix[c4];
                float4 vv;
                vv.x = fmaf(s, iv.x, mv.x);
                vv.y = fmaf(s, iv.y, mv.y);
                vv.z = fmaf(s, iv.z, mv.z);
                vv.w = fmaf(s, iv.w, mv.w);
                v[j] = vv;
                ssq = fmaf(vv.x, vv.x, ssq);
                ssq = fmaf(vv.y, vv.y, ssq);
                ssq = fmaf(vv.z, vv.z, ssq);
                ssq = fmaf(vv.w, vv.w, ssq);
            }
        }
        float tot = blockReduceSumB(ssq);
        float inv = 1.0f / (sqrtf(tot) + 1e-12f);
        float4* dst = reinterpret_cast<float4*>(out_neu) + (size_t)r * NV4;
#pragma unroll
        for (int j = 0; j < 7; j++) {
            int c4 = t + j * 256;
            if (c4 < NV4) {
                float4 o = v[j];
                o.x *= inv; o.y *= inv; o.z *= inv; o.w *= inv;
                __stcs(dst + c4, o);
            }
        }
        return;
    }

    // ======== control / producer blocks ========
    if (b < B_DOTS) {
        // ---- mix_x reduce: 7 blocks over NV4 float4 columns ----
        int c4 = b * 256 + t;
        if (c4 < NV4) {
            float4 mx = {0,0,0,0};
#pragma unroll
            for (int ch = 0; ch < NCHUNK; ch++) {
                float4 p = g_part4[ch][c4];
                mx.x += p.x; mx.y += p.y; mx.z += p.z; mx.w += p.w;
            }
            reinterpret_cast<float4*>(g_mix_x)[c4] = mx;
        }
        signalCnt(&c_red);
        return;
    }

    if (b == B_DOTS) {
        waitCnt(&c_red, 7);
        float dxx = 0.0f, dxi = 0.0f, dii = 0.0f;
        for (int i = t; i < DD; i += 256) {
            float m = g_mix_x[i];
            float p = g_inpt[i];
            dxx = fmaf(m, m, dxx);
            dxi = fmaf(m, p, dxi);
            dii = fmaf(p, p, dii);
        }
        float sxx = blockReduceSumB(dxx);
        float sxi = blockReduceSumB(dxi);
        float sii = blockReduceSumB(dii);
        if (t == 0) { g_dots[0] = sxx; g_dots[1] = sxi; g_dots[2] = sii; }
        signalCnt(&c_dots);
        return;
    }

    if (b >= B_YC0 && b < B_YC0 + YBLK) {
        // ---- y candidates: key-rank over 256 ----
        __shared__ u64 sk[256];
        int w = b - B_YC0;
        int row = XS + w * 256 + t;
        u64 key = makeKey(g_resp[row], row);
        sk[t] = key;
        __syncthreads();
        int rank = 0;
#pragma unroll 8
        for (int j = 0; j < 256; j++) rank += (sk[j] > key);
        if (rank < TK + 1) g_ckey[w][rank] = key;
        signalCnt(&c_yc);
        return;
    }

    if (b == B_Z) {
        // ---- z top-9 + z finals ----
        __shared__ u64   zk[ZS];
        __shared__ float s_zv[ZTK + 1];
        __shared__ int   s_zr[ZTK + 1];
        if (t < ZS) {
            int row = XS + NN + t;
            zk[t] = makeKey(g_resp[row], row);
        }
        __syncthreads();
        if (t < ZS) {
            u64 key = zk[t];
            int rank = 0;
#pragma unroll
            for (int j = 0; j < ZS; j++) rank += (zk[j] > key);
            if (rank < ZTK + 1) {
                float v = keyVal(key); int row = keyRow(key);
                s_zv[rank] = v; s_zr[rank] = row;
                g_zval[rank] = v; g_zrow[rank] = row;
            }
        }
        __syncthreads();
        if (t < ZTK) {
            float zvL = s_zv[ZTK];
            float dz = 1.0f / (s_zv[0] - zvL);
            int r = s_zr[t];
            float f = (s_zv[t] - zvL) * dz;
            out_final[r] = f;
            out_z[r - (XS + NN)] = f;
            out_ages[r] = ages[r] + 1.0f;
        }
        signalCnt(&c_z);
        return;
    }

    if (b == B_XM) {
        // ---- x max + nonzero -> g_inv_dx ----
        __shared__ float s_xv[8];
        __shared__ int   s_xnz[8];
        int lane = t & 31;
        int wid  = t >> 5;
        float bv = -FLT_MAX; int nz = 0;
#pragma unroll
        for (int j = 0; j < 8; j++) {
            float v = g_resp[t + j * 256];
            bv = fmaxf(bv, v);
            nz |= (v != 0.0f);
        }
#pragma unroll
        for (int o = 16; o > 0; o >>= 1) {
            bv  = fmaxf(bv, __shfl_down_sync(0xffffffffu, bv, o));
            nz |= __shfl_down_sync(0xffffffffu, nz, o);
        }
        if (lane == 0) { s_xv[wid] = bv; s_xnz[wid] = nz; }
        __syncthreads();
        if (t == 0) {
            float m = s_xv[0]; int z2 = s_xnz[0];
#pragma unroll
            for (int w2 = 1; w2 < 8; w2++) { m = fmaxf(m, s_xv[w2]); z2 |= s_xnz[w2]; }
            float tx = z2 ? 0.0f : 1.0f;
            g_inv_dx = 1.0f / (m + EPSF * tx * RNDF);
        }
        signalCnt(&c_x);
        return;
    }

    if (b == B_YM) {
        // ---- y merge: rank over 272 candidates (2 per thread) + finals ----
        __shared__ u64   s_k[NCAND];
        __shared__ float s_yv[TK + 1];
        __shared__ int   s_yr[TK + 1];
        waitCnt(&c_yc, YBLK);
        s_k[t] = ((const u64*)g_ckey)[t];
        if (t < NCAND - 256) s_k[256 + t] = ((const u64*)g_ckey)[256 + t];
        __syncthreads();
#pragma unroll 1
        for (int pass = 0; pass < 2; pass++) {
            int idx = t + pass * 256;
            if (idx < NCAND) {
                u64 key = s_k[idx];
                int rank = 0;
#pragma unroll 8
                for (int j = 0; j < NCAND; j++) rank += (s_k[j] > key);
                if (rank < TK + 1) {
                    float v = keyVal(key); int row = keyRow(key);
                    s_yv[rank] = v; s_yr[rank] = row;
                    g_yval[rank] = v; g_yrow[rank] = row;
                }
            }
        }
        __syncthreads();
        if (t < 32) {
            float yvL = s_yv[TK];
            bool tie = (t < TK) && (s_yv[t] == yvL);
            u32 bal = __ballot_sync(0xffffffffu, tie);
            float ty = bal ? 1.0f : 0.0f;
            if (t < TK) {
                float dy = 1.0f / (s_yv[0] - yvL + EPSF * ty * RNDF);
                int r = s_yr[t];
                out_final[r] = (s_yv[t] - yvL) * dy;
                out_ages[r]  = ages[r] + 1.0f;
            }
        }
        signalCnt(&c_y);
        return;
    }

    // ---- b in B_MYZ0..B_MYZ0+6: mix_y / mix_z ----
    {
        waitCnt(&c_y, 1);
        waitCnt(&c_z, 1);
        int c4 = (b - B_MYZ0) * 256 + t;
        if (c4 < NV4) {
            float4 my = {0,0,0,0};
#pragma unroll
            for (int k = 0; k < TK; k++) {
                int r = g_yrow[k];
                float w = g_w[r];
                float4 v = __ldg(&neu4[(size_t)r * NV4 + c4]);
                my.x = fmaf(w, v.x, my.x); my.y = fmaf(w, v.y, my.y);
                my.z = fmaf(w, v.z, my.z); my.w = fmaf(w, v.w, my.w);
            }
            reinterpret_cast<float4*>(g_mix_y)[c4] = my;

            float4 mz = {0,0,0,0};
#pragma unroll
            for (int k = 0; k < ZTK; k++) {
                int r = g_zrow[k];
                float w = g_w[r];
                float4 v = __ldg(&neu4[(size_t)r * NV4 + c4]);
                mz.x = fmaf(w, v.x, mz.x); mz.y = fmaf(w, v.y, mz.y);
                mz.z = fmaf(w, v.z, mz.z); mz.w = fmaf(w, v.w, mz.w);
            }
            reinterpret_cast<float4*>(g_mix_z)[c4] = mz;
        }
        signalCnt(&c_myz);
        return;
    }
}

// ---------------- launch ----------------
extern "C" void kernel_launch(void* const* d_in, const int* in_sizes, int n_in,
                              void* d_out, int out_size) {
    (void)in_sizes; (void)n_in; (void)out_size;
    const float* x       = (const float*)d_in[0];
    const float* z       = (const float*)d_in[1];
    const float* yresp   = (const float*)d_in[2];
    const float* neurons = (const float*)d_in[3];
    const float* ages    = (const float*)d_in[4];

    float* out       = (float*)d_out;
    float* out_z     = out;                                // 64
    float* out_final = out + ZS;                           // 6208
    float* out_neu   = out + ZS + DD;                      // 6208*6208
    float* out_ages  = out + ZS + DD + (size_t)DD * DD;    // 6208

    k_init<<<(DD + 255) / 256, 256>>>(x, z, yresp, ages, out_z, out_final, out_ages);
    k_main<<<MIXBLK + DD, 256>>>((const float4*)neurons, out_neu);
    k_post<<<NPOST, 256>>>(ages, (const float4*)neurons, out_z, out_final, out_ages, out_neu);
}